// round 1
// baseline (speedup 1.0000x reference)
#include <cuda_runtime.h>
#include <cuda_bf16.h>

#define N_NODES 131072
#define N_EDGES 524288
#define NQ      64

// ---------------- device scratch ----------------
__device__ float    g_Hl[N_NODES * 64];
__device__ float    g_Hr[N_NODES * 64];
__device__ float    g_qtl[NQ * 64];
__device__ float    g_qtr[NQ * 64];
__device__ float    g_logits[N_EDGES];
__device__ float    g_ex[N_EDGES];
__device__ float    g_sm[N_EDGES];
__device__ float    g_ta[N_EDGES];
__device__ unsigned g_segmax[N_NODES];
__device__ float    g_segsum[N_NODES];
__device__ float    g_score[N_NODES];
__device__ float    g_egsum[NQ];
__device__ unsigned g_cnt[4 * NQ * 256];
__device__ unsigned g_prefix[NQ];
__device__ int      g_krem[NQ];
__device__ float    g_kth[NQ];
__device__ int      g_done[NQ];

// ---------------- helpers ----------------
__device__ __forceinline__ unsigned fkey(float f) {
    unsigned b = __float_as_uint(f);
    return b ^ ((unsigned)((int)b >> 31) | 0x80000000u);
}
__device__ __forceinline__ float fdec(unsigned u) {
    unsigned b = (u & 0x80000000u) ? (u ^ 0x80000000u) : ~u;
    return __uint_as_float(b);
}
__device__ __forceinline__ float lrelu(float x) { return x > 0.f ? x : 0.01f * x; }

#define SMPAD 68   // padded row stride (floats), multiple of 4 for float4 alignment

// load 64x64 chunk of row-major W into As[o][k] (row stride SMPAD)
__device__ __forceinline__ void load_A64(float* As, const float* __restrict__ W,
                                         int ldw, int koff, int tid) {
#pragma unroll
    for (int i = 0; i < 4; i++) {
        int o  = (tid >> 4) + i * 16;
        int k4 = (tid & 15) * 4;
        float4 v = *reinterpret_cast<const float4*>(&W[o * ldw + koff + k4]);
        *reinterpret_cast<float4*>(&As[o * SMPAD + k4]) = v;
    }
}
// load 64 items x 64 k chunk of row-major G into Bs[k][item]
__device__ __forceinline__ void load_B64(float* Bs, const float* __restrict__ G,
                                         int ldg, int i0, int koff, int tid) {
#pragma unroll
    for (int i = 0; i < 4; i++) {
        int item = (tid >> 4) + i * 16;
        int k4   = (tid & 15) * 4;
        float4 v = *reinterpret_cast<const float4*>(&G[(i0 + item) * ldg + koff + k4]);
        Bs[(k4 + 0) * SMPAD + item] = v.x;
        Bs[(k4 + 1) * SMPAD + item] = v.y;
        Bs[(k4 + 2) * SMPAD + item] = v.z;
        Bs[(k4 + 3) * SMPAD + item] = v.w;
    }
}
// acc[4][4] += A(64xk64) * B(k64 x 64) micro-tile at (ty,tx)
__device__ __forceinline__ void gemm64(const float* __restrict__ As,
                                       const float* __restrict__ Bs,
                                       float acc[4][4], int ty, int tx) {
#pragma unroll 8
    for (int kk = 0; kk < 64; ++kk) {
        float a0 = As[(ty * 4 + 0) * SMPAD + kk];
        float a1 = As[(ty * 4 + 1) * SMPAD + kk];
        float a2 = As[(ty * 4 + 2) * SMPAD + kk];
        float a3 = As[(ty * 4 + 3) * SMPAD + kk];
        float4 b = *reinterpret_cast<const float4*>(&Bs[kk * SMPAD + tx * 4]);
        acc[0][0] += a0 * b.x; acc[0][1] += a0 * b.y; acc[0][2] += a0 * b.z; acc[0][3] += a0 * b.w;
        acc[1][0] += a1 * b.x; acc[1][1] += a1 * b.y; acc[1][2] += a1 * b.z; acc[1][3] += a1 * b.w;
        acc[2][0] += a2 * b.x; acc[2][1] += a2 * b.y; acc[2][2] += a2 * b.z; acc[2][3] += a2 * b.w;
        acc[3][0] += a3 * b.x; acc[3][1] += a3 * b.y; acc[3][2] += a3 * b.z; acc[3][3] += a3 * b.w;
    }
}

// ---------------- zero/init ----------------
__global__ void k_zero() {
    int i = blockIdx.x * blockDim.x + threadIdx.x;
    int stride = gridDim.x * blockDim.x;
    for (int j = i; j < N_NODES; j += stride) {
        g_segmax[j] = 0u; g_segsum[j] = 0.f; g_score[j] = 0.f;
    }
    for (int j = i; j < 4 * NQ * 256; j += stride) g_cnt[j] = 0u;
    if (i < NQ) g_egsum[i] = 0.f;
}

// ---------------- per-query tails ----------------
__global__ void k_query(const float* __restrict__ qsrc, const float* __restrict__ qrel,
                        const float* __restrict__ qtime,
                        const float* __restrict__ Ws, const float* __restrict__ bs,
                        const float* __restrict__ Wt, const float* __restrict__ bt,
                        const float* __restrict__ Wp, const float* __restrict__ bp,
                        const float* __restrict__ Wl, const float* __restrict__ bl,
                        const float* __restrict__ Wr, const float* __restrict__ br) {
    __shared__ float tail[128];
    __shared__ float inS[512];
    int b = blockIdx.x, t = threadIdx.x;  // 64 threads
    float* srcS  = inS;        // 128
    float* relS  = inS + 128;  // 256
    float* timeS = inS + 384;  // 128
    for (int i = t; i < 128; i += 64) srcS[i]  = qsrc[b * 128 + i];
    for (int i = t; i < 256; i += 64) relS[i]  = qrel[b * 256 + i];
    for (int i = t; i < 128; i += 64) timeS[i] = qtime[b * 128 + i];
    __syncthreads();
    if (t < 32) {
        float s = bs[t];
        for (int k = 0; k < 128; k++) s += Ws[t * 128 + k] * srcS[k];
        tail[t] = s;
        float s2 = bt[t];
        for (int k = 0; k < 128; k++) s2 += Wt[t * 128 + k] * timeS[k];
        tail[96 + t] = s2;
    }
    {
        float s = bp[t];
        for (int k = 0; k < 256; k++) s += Wp[t * 256 + k] * relS[k];
        tail[32 + t] = s;
    }
    __syncthreads();
    float sl = bl[t], sr = br[t];
    for (int k = 0; k < 128; k++) {
        float tv = tail[k];
        sl += Wl[t * 256 + 128 + k] * tv;
        sr += Wr[t * 256 + 128 + k] * tv;
    }
    g_qtl[b * 64 + t] = sl;
    g_qtr[b * 64 + t] = sr;
}

// ---------------- per-node precompute: Hl = Wl1@(Wp@mem+bp), Hr = Wr1@(...) ----------------
__global__ void __launch_bounds__(256) k_node(const float* __restrict__ mem,
                                              const float* __restrict__ Wp,
                                              const float* __restrict__ bp,
                                              const float* __restrict__ Wl,
                                              const float* __restrict__ Wr) {
    extern __shared__ float smem[];
    float* As = smem;                 // 64*SMPAD
    float* Bs = smem + 64 * SMPAD;    // 64*SMPAD
    int tid = threadIdx.x, ty = tid >> 4, tx = tid & 15;
    int n0 = blockIdx.x * 64;

    float acc[4][4];
    float4 bp4 = *reinterpret_cast<const float4*>(&bp[ty * 4]);
    float bpv[4] = {bp4.x, bp4.y, bp4.z, bp4.w};
#pragma unroll
    for (int i = 0; i < 4; i++)
#pragma unroll
        for (int j = 0; j < 4; j++) acc[i][j] = bpv[i];

    for (int kc = 0; kc < 4; kc++) {
        __syncthreads();
        load_A64(As, Wp, 256, kc * 64, tid);
        load_B64(Bs, mem, 256, n0, kc * 64, tid);
        __syncthreads();
        gemm64(As, Bs, acc, ty, tx);
    }
    __syncthreads();
    // hv tile -> Bs ([hvdim][node]) ; also load Wl1 into As
#pragma unroll
    for (int i = 0; i < 4; i++) {
        float4 v = make_float4(acc[i][0], acc[i][1], acc[i][2], acc[i][3]);
        *reinterpret_cast<float4*>(&Bs[(ty * 4 + i) * SMPAD + tx * 4]) = v;
    }
    load_A64(As, Wl, 256, 0, tid);
    __syncthreads();
    float a2[4][4];
#pragma unroll
    for (int i = 0; i < 4; i++)
#pragma unroll
        for (int j = 0; j < 4; j++) a2[i][j] = 0.f;
    gemm64(As, Bs, a2, ty, tx);
#pragma unroll
    for (int j = 0; j < 4; j++) {
        int n = n0 + tx * 4 + j;
        float4 v = make_float4(a2[0][j], a2[1][j], a2[2][j], a2[3][j]);
        *reinterpret_cast<float4*>(&g_Hl[n * 64 + ty * 4]) = v;
    }
    __syncthreads();
    load_A64(As, Wr, 256, 0, tid);
    __syncthreads();
#pragma unroll
    for (int i = 0; i < 4; i++)
#pragma unroll
        for (int j = 0; j < 4; j++) a2[i][j] = 0.f;
    gemm64(As, Bs, a2, ty, tx);
#pragma unroll
    for (int j = 0; j < 4; j++) {
        int n = n0 + tx * 4 + j;
        float4 v = make_float4(a2[0][j], a2[1][j], a2[2][j], a2[3][j]);
        *reinterpret_cast<float4*>(&g_Hr[n * 64 + ty * 4]) = v;
    }
}

// ---------------- fused edge kernel: r, L, R, C, logits, segmax ----------------
__global__ void __launch_bounds__(256) k_edge(const float* __restrict__ rel,
                                              const int* __restrict__ esrc,
                                              const int* __restrict__ edst,
                                              const int* __restrict__ eeg,
                                              const float* __restrict__ Wp,
                                              const float* __restrict__ bp,
                                              const float* __restrict__ Wl,
                                              const float* __restrict__ Wr,
                                              const float* __restrict__ Wc,
                                              const float* __restrict__ bc) {
    extern __shared__ float smem[];
    float* As = smem;                    // 64*SMPAD
    float* Bs = As + 64 * SMPAD;         // 64*SMPAD (rel chunk, reused as R)
    float* rS = Bs + 64 * SMPAD;         // 64*SMPAD (r tile, [rdim][edge])
    float* logitS = rS + 64 * SMPAD;     // 64
    int* sS = (int*)(logitS + 64);
    int* dS = sS + 64;
    int* gS = dS + 64;

    int tid = threadIdx.x, ty = tid >> 4, tx = tid & 15;
    int e0 = blockIdx.x * 64;
    if (tid < 64) {
        sS[tid] = esrc[e0 + tid];
        dS[tid] = edst[e0 + tid];
        gS[tid] = eeg[e0 + tid];
        logitS[tid] = 0.f;
    }

    float acc[4][4];
    float4 bp4 = *reinterpret_cast<const float4*>(&bp[ty * 4]);
    float bpv[4] = {bp4.x, bp4.y, bp4.z, bp4.w};
#pragma unroll
    for (int i = 0; i < 4; i++)
#pragma unroll
        for (int j = 0; j < 4; j++) acc[i][j] = bpv[i];

    // GEMM1: r = Wp @ rel_tile + bp
    for (int kc = 0; kc < 4; kc++) {
        __syncthreads();
        load_A64(As, Wp, 256, kc * 64, tid);
        load_B64(Bs, rel, 256, e0, kc * 64, tid);
        __syncthreads();
        gemm64(As, Bs, acc, ty, tx);
    }
    __syncthreads();
#pragma unroll
    for (int i = 0; i < 4; i++) {
        float4 v = make_float4(acc[i][0], acc[i][1], acc[i][2], acc[i][3]);
        *reinterpret_cast<float4*>(&rS[(ty * 4 + i) * SMPAD + tx * 4]) = v;
    }
    load_A64(As, Wr, 256, 64, tid);   // Wr2
    __syncthreads();

    // GEMM2a: R = lrelu(Wr2@r + Hr[dst] + qtr[eg])
#pragma unroll
    for (int j = 0; j < 4; j++) {
        int e = tx * 4 + j;
        int d = dS[e], g = gS[e];
        float4 h = *reinterpret_cast<const float4*>(&g_Hr[d * 64 + ty * 4]);
        float4 q = *reinterpret_cast<const float4*>(&g_qtr[g * 64 + ty * 4]);
        acc[0][j] = h.x + q.x; acc[1][j] = h.y + q.y;
        acc[2][j] = h.z + q.z; acc[3][j] = h.w + q.w;
    }
    gemm64(As, rS, acc, ty, tx);
    __syncthreads();   // all As reads done; Bs free to be overwritten below
#pragma unroll
    for (int i = 0; i < 4; i++) {
        float4 v = make_float4(lrelu(acc[i][0]), lrelu(acc[i][1]),
                               lrelu(acc[i][2]), lrelu(acc[i][3]));
        *reinterpret_cast<float4*>(&Bs[(ty * 4 + i) * SMPAD + tx * 4]) = v;
    }
    load_A64(As, Wc, 64, 0, tid);
    __syncthreads();

    // GEMM3: C = Wc@R + bc
    float cc[4][4];
    float4 bc4 = *reinterpret_cast<const float4*>(&bc[ty * 4]);
    float bcv[4] = {bc4.x, bc4.y, bc4.z, bc4.w};
#pragma unroll
    for (int i = 0; i < 4; i++)
#pragma unroll
        for (int j = 0; j < 4; j++) cc[i][j] = bcv[i];
    gemm64(As, Bs, cc, ty, tx);
    __syncthreads();
    load_A64(As, Wl, 256, 64, tid);   // Wl2
    __syncthreads();

    // GEMM2b: L = lrelu(Wl2@r + Hl[src] + qtl[eg])
#pragma unroll
    for (int j = 0; j < 4; j++) {
        int e = tx * 4 + j;
        int s = sS[e], g = gS[e];
        float4 h = *reinterpret_cast<const float4*>(&g_Hl[s * 64 + ty * 4]);
        float4 q = *reinterpret_cast<const float4*>(&g_qtl[g * 64 + ty * 4]);
        acc[0][j] = h.x + q.x; acc[1][j] = h.y + q.y;
        acc[2][j] = h.z + q.z; acc[3][j] = h.w + q.w;
    }
    gemm64(As, rS, acc, ty, tx);

    // partial dot L·C
    float p[4] = {0.f, 0.f, 0.f, 0.f};
#pragma unroll
    for (int i = 0; i < 4; i++)
#pragma unroll
        for (int j = 0; j < 4; j++) p[j] += lrelu(acc[i][j]) * cc[i][j];
#pragma unroll
    for (int j = 0; j < 4; j++) atomicAdd(&logitS[tx * 4 + j], p[j]);
    __syncthreads();

    if (tid < 64) {
        float v = logitS[tid];
        g_logits[e0 + tid] = v;
        atomicMax(&g_segmax[sS[tid]], fkey(v));
    }
}

// ---------------- softmax / pruning pipeline ----------------
__global__ void k_exp(const int* __restrict__ esrc) {
    int e = blockIdx.x * blockDim.x + threadIdx.x;
    if (e >= N_EDGES) return;
    int s = esrc[e];
    float m = fdec(g_segmax[s]);
    float ex = expf(g_logits[e] - m);
    g_ex[e] = ex;
    atomicAdd(&g_segsum[s], ex);
}

__global__ void k_smta(const int* __restrict__ esrc, const int* __restrict__ eeg,
                       const float* __restrict__ natt) {
    int e = blockIdx.x * blockDim.x + threadIdx.x;
    if (e >= N_EDGES) return;
    int s = esrc[e];
    float smv = g_ex[e] / (g_segsum[s] + 1e-12f);
    float ta = smv * natt[s];
    g_sm[e] = smv;
    g_ta[e] = ta;
    unsigned key = fkey(ta);
    atomicAdd(&g_cnt[(unsigned)eeg[e] * 256u + (key >> 24)], 1u);
}

__global__ void k_hist(const int* __restrict__ eeg, int pass) {
    int e = blockIdx.x * blockDim.x + threadIdx.x;
    if (e >= N_EDGES) return;
    int b = eeg[e];
    unsigned key = fkey(g_ta[e]);
    if ((key >> (32 - 8 * pass)) == g_prefix[b]) {
        atomicAdd(&g_cnt[pass * NQ * 256 + b * 256 + ((key >> (24 - 8 * pass)) & 255)], 1u);
    }
}

__global__ void k_resolve(int pass, const int* __restrict__ pk) {
    int b = threadIdx.x;
    if (b >= NQ) return;
    if (pass > 0 && g_done[b]) return;
    int k;
    if (pass == 0) {
        k = pk ? *pk : 1024;
        if (k < 1) k = 1;
    } else {
        k = g_krem[b];
    }
    const unsigned* base = g_cnt + pass * NQ * 256 + b * 256;
    int cum = 0, d;
    for (d = 255; d >= 0; --d) {
        int c = (int)base[d];
        if (cum + c >= k) break;
        cum += c;
    }
    if (d < 0) {  // fewer than k edges for this query -> keep all
        g_done[b] = 1;
        g_kth[b] = -3.0e38f;
        return;
    }
    if (pass == 0) g_done[b] = 0;
    unsigned pref = (pass == 0) ? 0u : g_prefix[b];
    g_prefix[b] = (pref << 8) | (unsigned)d;
    g_krem[b] = k - cum;
    if (pass == 3) g_kth[b] = fdec(g_prefix[b]);
}

__global__ void k_contrib(const int* __restrict__ eeg, const int* __restrict__ edst) {
    int e = blockIdx.x * blockDim.x + threadIdx.x;
    if (e >= N_EDGES) return;
    float ta = g_ta[e];
    if (ta >= g_kth[eeg[e]]) {
        atomicAdd(&g_score[edst[e]], g_sm[e] * ta);
    }
}

__global__ void k_egsum(const int* __restrict__ n2e) {
    __shared__ float bins[NQ];
    int tid = threadIdx.x;
    if (tid < NQ) bins[tid] = 0.f;
    __syncthreads();
    int i = blockIdx.x * blockDim.x + tid;
    int stride = gridDim.x * blockDim.x;
    for (int n = i; n < N_NODES; n += stride) {
        atomicAdd(&bins[n2e[n]], g_score[n]);
    }
    __syncthreads();
    if (tid < NQ) atomicAdd(&g_egsum[tid], bins[tid]);
}

__global__ void k_out(const int* __restrict__ n2e, float* __restrict__ out) {
    int n = blockIdx.x * blockDim.x + threadIdx.x;
    if (n >= N_NODES) return;
    out[n] = g_score[n] / (g_egsum[n2e[n]] + 1e-12f);
}

// ---------------- host launch ----------------
extern "C" void kernel_launch(void* const* d_in, const int* in_sizes, int n_in,
                              void* d_out, int out_size) {
    const float* natt  = (const float*)d_in[0];
    const float* mem   = (const float*)d_in[1];
    const float* rel   = (const float*)d_in[2];
    const float* qsrc  = (const float*)d_in[3];
    const float* qrel  = (const float*)d_in[4];
    const float* qtime = (const float*)d_in[5];
    const int*   eeg   = (const int*)d_in[6];
    const int*   esrc  = (const int*)d_in[7];
    const int*   edst  = (const int*)d_in[8];
    const int*   n2e   = (const int*)d_in[9];
    const float* Wp  = (const float*)d_in[10];
    const float* bp  = (const float*)d_in[11];
    const float* Ws_ = (const float*)d_in[12];
    const float* bs  = (const float*)d_in[13];
    const float* Wt  = (const float*)d_in[14];
    const float* bt  = (const float*)d_in[15];
    const float* Wl  = (const float*)d_in[16];
    const float* bl  = (const float*)d_in[17];
    const float* Wr  = (const float*)d_in[18];
    const float* br  = (const float*)d_in[19];
    const float* Wc  = (const float*)d_in[20];
    const float* bc  = (const float*)d_in[21];
    const int*   pk  = (n_in > 22) ? (const int*)d_in[22] : nullptr;
    float* out = (float*)d_out;

    const int SMEM_NODE = 2 * 64 * SMPAD * (int)sizeof(float);
    const int SMEM_EDGE = (3 * 64 * SMPAD + 64) * (int)sizeof(float) + 3 * 64 * (int)sizeof(int);

    cudaFuncSetAttribute(k_edge, cudaFuncAttributeMaxDynamicSharedMemorySize, SMEM_EDGE);
    cudaFuncSetAttribute(k_node, cudaFuncAttributeMaxDynamicSharedMemorySize, SMEM_NODE);

    k_zero<<<512, 256>>>();
    k_query<<<NQ, 64>>>(qsrc, qrel, qtime, Ws_, bs, Wt, bt, Wp, bp, Wl, bl, Wr, br);
    k_node<<<N_NODES / 64, 256, SMEM_NODE>>>(mem, Wp, bp, Wl, Wr);
    k_edge<<<N_EDGES / 64, 256, SMEM_EDGE>>>(rel, esrc, edst, eeg, Wp, bp, Wl, Wr, Wc, bc);
    k_exp<<<N_EDGES / 256, 256>>>(esrc);
    k_smta<<<N_EDGES / 256, 256>>>(esrc, eeg, natt);
    k_resolve<<<1, 64>>>(0, pk);
    for (int p = 1; p <= 3; p++) {
        k_hist<<<N_EDGES / 256, 256>>>(eeg, p);
        k_resolve<<<1, 64>>>(p, pk);
    }
    k_contrib<<<N_EDGES / 256, 256>>>(eeg, edst);
    k_egsum<<<256, 256>>>(n2e);
    k_out<<<N_NODES / 256, 256>>>(n2e, out);
}